// round 2
// baseline (speedup 1.0000x reference)
#include <cuda_runtime.h>
#include <math.h>

// Problem constants (fixed by the dataset): inputs [4096, 2048] fp32, targets [4096]
#define NN 4096
#define DD 2048

// GEMM tiling
#define BM 64
#define BN 64
#define BK 16
#define TM 4
#define TN 4
#define STRIPS 8
#define CPS (NN / STRIPS)   // columns per strip = 512

// Scratch (no cudaMalloc allowed)
__device__ float        g_sq[NN];
__device__ int          g_tgt[NN];
__device__ unsigned int g_ap[NN];   // hardest-positive dist (max), bits of positive float
__device__ unsigned int g_an[NN];   // hardest-negative dist (min)

// ---------------------------------------------------------------------------
// Init per-row reduction state (graph-replay safe: runs every launch)
// ---------------------------------------------------------------------------
__global__ void init_kernel() {
    int i = blockIdx.x * blockDim.x + threadIdx.x;
    if (i < NN) {
        g_ap[i] = 0u;            // dist >= 0 always; max starts at 0
        g_an[i] = 0x7f800000u;   // +inf
    }
}

// ---------------------------------------------------------------------------
// Targets: detect int64 vs int32 on device, normalize into g_tgt as int32.
// If the buffer is int64 (little-endian, values 0..255), every odd 32-bit word
// of the first NN words is the zero high-half. For genuine int32 random labels
// that is statistically impossible. No OOB in either case:
//   int64 path reads word 2*i   for i < NN   -> max word 8190 < 2*NN
//   int32 path reads word 2*i+1 for i < NN/2 -> max word 4095 < NN
// ---------------------------------------------------------------------------
__global__ void tgt_kernel(const int* __restrict__ t) {
    __shared__ int is64;
    if (threadIdx.x == 0) is64 = 1;
    __syncthreads();
    for (int i = threadIdx.x; i < NN / 2; i += blockDim.x) {
        if (t[2 * i + 1] != 0) is64 = 0;   // benign race: all writers store 0
    }
    __syncthreads();
    const int e = is64;
    for (int i = threadIdx.x; i < NN; i += blockDim.x) {
        g_tgt[i] = e ? t[2 * i] : t[i];
    }
}

// ---------------------------------------------------------------------------
// Row squared norms
// ---------------------------------------------------------------------------
__global__ void sq_kernel(const float* __restrict__ A) {
    const int row = blockIdx.x;
    const float4* a = (const float4*)(A + (size_t)row * DD);
    float s = 0.f;
    for (int j = threadIdx.x; j < DD / 4; j += blockDim.x) {
        float4 v = a[j];
        s += v.x * v.x + v.y * v.y + v.z * v.z + v.w * v.w;
    }
    #pragma unroll
    for (int off = 16; off > 0; off >>= 1)
        s += __shfl_xor_sync(0xffffffffu, s, off);
    __shared__ float ws[8];
    const int lane = threadIdx.x & 31, w = threadIdx.x >> 5;
    if (lane == 0) ws[w] = s;
    __syncthreads();
    if (threadIdx.x == 0) {
        float t = 0.f;
        #pragma unroll
        for (int i = 0; i < 8; i++) t += ws[i];
        g_sq[row] = t;
    }
}

// ---------------------------------------------------------------------------
// Fused Gram-matrix GEMM + masked hardest-positive / hardest-negative mining.
// Block: 256 threads (16x16), each thread owns a 4x4 output sub-tile.
// Grid: (STRIPS, NN/BM). Each block covers BM rows x CPS columns.
// Per-row partial max/min reduced across the 16 column-threads via half-warp
// butterfly shuffles, then one atomic per row per block.
// ---------------------------------------------------------------------------
__global__ void __launch_bounds__(256, 2) tri_kernel(const float* __restrict__ A) {
    __shared__ float As[BK][BM];
    __shared__ float Bs[BK][BN];
    __shared__ float sqB[BN];
    __shared__ int   tgtB[BN];

    const int tid = threadIdx.x;
    const int tx  = tid & 15;
    const int ty  = tid >> 4;
    const int row0  = blockIdx.y * BM;
    const int cbase = blockIdx.x * CPS;

    // cooperative tile-load mapping: thread -> (row-in-tile, k-quad)
    const int lm = tid >> 2;         // 0..63
    const int lk = (tid & 3) << 2;   // 0,4,8,12

    float rowsq[TM];
    int   rowt[TM];
    #pragma unroll
    for (int i = 0; i < TM; i++) {
        const int r = row0 + ty * TM + i;
        rowsq[i] = g_sq[r];
        rowt[i]  = g_tgt[r];
    }

    float ap[TM], an[TM];
    #pragma unroll
    for (int i = 0; i < TM; i++) {
        ap[i] = 0.f;
        an[i] = __int_as_float(0x7f800000);
    }

    for (int ct = 0; ct < CPS; ct += BN) {
        const int col0 = cbase + ct;
        if (tid < BN) {
            tgtB[tid] = g_tgt[col0 + tid];
            sqB[tid]  = g_sq[col0 + tid];
        }

        float acc[TM][TN];
        #pragma unroll
        for (int i = 0; i < TM; i++)
            #pragma unroll
            for (int j = 0; j < TN; j++) acc[i][j] = 0.f;

        for (int k0 = 0; k0 < DD; k0 += BK) {
            float4 va = *(const float4*)(A + (size_t)(row0 + lm) * DD + k0 + lk);
            float4 vb = *(const float4*)(A + (size_t)(col0 + lm) * DD + k0 + lk);
            As[lk + 0][lm] = va.x; As[lk + 1][lm] = va.y;
            As[lk + 2][lm] = va.z; As[lk + 3][lm] = va.w;
            Bs[lk + 0][lm] = vb.x; Bs[lk + 1][lm] = vb.y;
            Bs[lk + 2][lm] = vb.z; Bs[lk + 3][lm] = vb.w;
            __syncthreads();

            #pragma unroll
            for (int k = 0; k < BK; k++) {
                float ra[TM], rb[TN];
                #pragma unroll
                for (int i = 0; i < TM; i++) ra[i] = As[k][ty * TM + i];
                #pragma unroll
                for (int j = 0; j < TN; j++) rb[j] = Bs[k][tx * TN + j];
                #pragma unroll
                for (int i = 0; i < TM; i++)
                    #pragma unroll
                    for (int j = 0; j < TN; j++)
                        acc[i][j] = fmaf(ra[i], rb[j], acc[i][j]);
            }
            __syncthreads();
        }

        // epilogue: distance + mask + running hardest pos/neg
        #pragma unroll
        for (int i = 0; i < TM; i++) {
            #pragma unroll
            for (int j = 0; j < TN; j++) {
                const int   cj = tx * TN + j;
                const float d2 = rowsq[i] + sqB[cj] - 2.0f * acc[i][j];
                const float d  = sqrtf(fmaxf(d2, 1e-12f));
                if (rowt[i] == tgtB[cj]) ap[i] = fmaxf(ap[i], d);
                else                     an[i] = fminf(an[i], d);
            }
        }
        __syncthreads();   // protect tgtB/sqB before next tile overwrites
    }

    // reduce across the 16 column-threads (they sit in one half-warp)
    #pragma unroll
    for (int off = 8; off > 0; off >>= 1) {
        #pragma unroll
        for (int i = 0; i < TM; i++) {
            ap[i] = fmaxf(ap[i], __shfl_xor_sync(0xffffffffu, ap[i], off));
            an[i] = fminf(an[i], __shfl_xor_sync(0xffffffffu, an[i], off));
        }
    }
    if (tx == 0) {
        #pragma unroll
        for (int i = 0; i < TM; i++) {
            const int r = row0 + ty * TM + i;
            atomicMax(&g_ap[r], __float_as_uint(ap[i]));  // positive floats: uint order == float order
            atomicMin(&g_an[r], __float_as_uint(an[i]));
        }
    }
}

// ---------------------------------------------------------------------------
// Loss + precision
// ---------------------------------------------------------------------------
__global__ void finalize_kernel(float* __restrict__ out) {
    float l = 0.f, p = 0.f;
    for (int i = threadIdx.x; i < NN; i += blockDim.x) {
        const float a = __uint_as_float(g_ap[i]);
        const float n = __uint_as_float(g_an[i]);
        l += fmaxf(a - n + 0.3f, 0.f);
        p += (n > a) ? 1.f : 0.f;
    }
    #pragma unroll
    for (int off = 16; off > 0; off >>= 1) {
        l += __shfl_xor_sync(0xffffffffu, l, off);
        p += __shfl_xor_sync(0xffffffffu, p, off);
    }
    __shared__ float wl[8], wp[8];
    const int lane = threadIdx.x & 31, w = threadIdx.x >> 5;
    if (lane == 0) { wl[w] = l; wp[w] = p; }
    __syncthreads();
    if (threadIdx.x == 0) {
        float L = 0.f, P = 0.f;
        #pragma unroll
        for (int i = 0; i < 8; i++) { L += wl[i]; P += wp[i]; }
        out[0] = L / (float)NN;
        out[1] = P / (float)NN;
    }
}

// ---------------------------------------------------------------------------
extern "C" void kernel_launch(void* const* d_in, const int* in_sizes, int n_in,
                              void* d_out, int out_size) {
    const float* A   = (const float*)d_in[0];
    const int*   t32 = (const int*)d_in[1];   // int32 or int64; normalized on device
    float*       out = (float*)d_out;

    init_kernel<<<NN / 256, 256>>>();
    tgt_kernel<<<1, 256>>>(t32);
    sq_kernel<<<NN, 256>>>(A);

    dim3 grid(STRIPS, NN / BM);
    tri_kernel<<<grid, 256>>>(A);

    finalize_kernel<<<1, 256>>>(out);
}

// round 4
// speedup vs baseline: 9.2875x; 9.2875x over previous
#include <cuda_runtime.h>
#include <cuda_bf16.h>
#include <math.h>

// Problem constants: inputs [4096, 2048] fp32, targets [4096]
#define NN 4096
#define DD 2048
#define KA 4096                 // augmented K: [hi(2048) | lo(2048)] bf16
#define BM 128
#define BN 128
#define BK 32
#define STAGES 4
#define ROWB 80                 // 64B data + 16B pad per SMEM row (conflict-free)
#define TILE_BYTES (BM * ROWB)          // 10240
#define STAGE_BYTES (2 * TILE_BYTES)    // A + B
#define SMEM_DYN (STAGES * STAGE_BYTES) // 81920
#define NTILES 528              // lower triangle incl. diagonal of 32x32 tiles

// Scratch (no cudaMalloc allowed)
__device__ __nv_bfloat16 g_aug[(size_t)NN * KA];  // 32MB, row-major [i][k]
__device__ float        g_sq[NN];
__device__ int          g_tgt[NN];
__device__ unsigned int g_ap[NN];
__device__ unsigned int g_an[NN];

// ---------------------------------------------------------------------------
// helpers
// ---------------------------------------------------------------------------
__device__ __forceinline__ unsigned s2u(const void* p) {
    unsigned a;
    asm("{ .reg .u64 t; cvta.to.shared.u64 t, %1; cvt.u32.u64 %0, t; }" : "=r"(a) : "l"(p));
    return a;
}
__device__ __forceinline__ void cpa16(unsigned dst, const void* src) {
    unsigned long long g;
    asm("cvta.to.global.u64 %0, %1;" : "=l"(g) : "l"(src));
    asm volatile("cp.async.cg.shared.global [%0], [%1], 16;" :: "r"(dst), "l"(g));
}
__device__ __forceinline__ void ldsm4(unsigned* r, unsigned addr) {
    asm volatile("ldmatrix.sync.aligned.m8n8.x4.shared.b16 {%0,%1,%2,%3}, [%4];"
        : "=r"(r[0]), "=r"(r[1]), "=r"(r[2]), "=r"(r[3]) : "r"(addr));
}
__device__ __forceinline__ void mma16816(float* c, const unsigned* a, unsigned b0, unsigned b1) {
    asm volatile("mma.sync.aligned.m16n8k16.row.col.f32.bf16.bf16.f32 "
        "{%0,%1,%2,%3}, {%4,%5,%6,%7}, {%8,%9}, {%0,%1,%2,%3};"
        : "+f"(c[0]), "+f"(c[1]), "+f"(c[2]), "+f"(c[3])
        : "r"(a[0]), "r"(a[1]), "r"(a[2]), "r"(a[3]), "r"(b0), "r"(b1));
}

// ---------------------------------------------------------------------------
__global__ void init_kernel() {
    int i = blockIdx.x * blockDim.x + threadIdx.x;
    if (i < NN) { g_ap[i] = 0u; g_an[i] = 0x7f800000u; }
}

// Targets: int64 vs int32 detection (proved correct in the passing baseline)
__global__ void tgt_kernel(const int* __restrict__ t) {
    __shared__ int is64;
    if (threadIdx.x == 0) is64 = 1;
    __syncthreads();
    for (int i = threadIdx.x; i < NN / 2; i += blockDim.x)
        if (t[2 * i + 1] != 0) is64 = 0;
    __syncthreads();
    const int e = is64;
    for (int i = threadIdx.x; i < NN; i += blockDim.x)
        g_tgt[i] = e ? t[2 * i] : t[i];
}

// fp32 -> augmented bf16 [hi | lo], plain row-major; fused row norms.
__global__ void conv_kernel(const float* __restrict__ A) {
    const int i = blockIdx.x;
    const int t = threadIdx.x;  // 0..255, cols [8t, 8t+8)
    const float4* ap = (const float4*)(A + (size_t)i * DD + t * 8);
    float4 v0 = ap[0], v1 = ap[1];
    float x[8] = {v0.x, v0.y, v0.z, v0.w, v1.x, v1.y, v1.z, v1.w};

    float s = 0.f;
    unsigned uh[4], ul[4];
    #pragma unroll
    for (int q = 0; q < 4; q++) {
        float a0 = x[2*q], a1 = x[2*q+1];
        s += a0 * a0 + a1 * a1;
        __nv_bfloat16 h0 = __float2bfloat16_rn(a0);
        __nv_bfloat16 h1 = __float2bfloat16_rn(a1);
        __nv_bfloat16 l0 = __float2bfloat16_rn(a0 - __bfloat162float(h0));
        __nv_bfloat16 l1 = __float2bfloat16_rn(a1 - __bfloat162float(h1));
        uh[q] = (unsigned)__bfloat16_as_ushort(h0) | ((unsigned)__bfloat16_as_ushort(h1) << 16);
        ul[q] = (unsigned)__bfloat16_as_ushort(l0) | ((unsigned)__bfloat16_as_ushort(l1) << 16);
    }
    *(uint4*)(g_aug + (size_t)i * KA + t * 8)        = make_uint4(uh[0], uh[1], uh[2], uh[3]);
    *(uint4*)(g_aug + (size_t)i * KA + DD + t * 8)   = make_uint4(ul[0], ul[1], ul[2], ul[3]);

    #pragma unroll
    for (int o = 16; o > 0; o >>= 1) s += __shfl_xor_sync(0xffffffffu, s, o);
    __shared__ float ws[8];
    const int lane = t & 31, w = t >> 5;
    if (lane == 0) ws[w] = s;
    __syncthreads();
    if (t == 0) {
        float tot = 0.f;
        #pragma unroll
        for (int k = 0; k < 8; k++) tot += ws[k];
        g_sq[i] = tot;
    }
}

// ---------------------------------------------------------------------------
// Fused Gram GEMM (mma.sync bf16, 128x128 tile, K'=4096) + hard mining.
// 256 threads = 8 warps in 2x4; warp tile 64x32; triangular tiles, both
// row-direction and (off-diagonal) column-direction mining per tile.
// ---------------------------------------------------------------------------
__global__ void __launch_bounds__(256) gram_kernel() {
    extern __shared__ unsigned char smem_dyn[];
    __shared__ unsigned s_rap[BM], s_ran[BM], s_cap[BN], s_can[BN];

    const int tid = threadIdx.x, lane = tid & 31, wid = tid >> 5;
    const int wm = wid >> 2, wn = wid & 3;

    // lower-triangle tile decode: id = mt(mt+1)/2 + nt
    int mt = 0, rem = blockIdx.x;
    while (rem >= mt + 1) { rem -= mt + 1; mt++; }
    const int nt = rem;
    const int m0 = mt * BM, n0 = nt * BN;

    const unsigned sbase = s2u(smem_dyn);
    const __nv_bfloat16* aug = g_aug;

    if (tid < BM) { s_rap[tid] = 0u; s_ran[tid] = 0x7f800000u; }
    if (tid < BN) { s_cap[tid] = 0u; s_can[tid] = 0x7f800000u; }

    float acc[4][4][4];
    #pragma unroll
    for (int a = 0; a < 4; a++)
        #pragma unroll
        for (int b = 0; b < 4; b++)
            #pragma unroll
            for (int c = 0; c < 4; c++) acc[a][b][c] = 0.f;

    // per-thread load slots: 2 ops x (A,B); idx -> row idx>>2, 16B-quad idx&3
    const int r_a = (tid + 0)   >> 2, q_a = (tid + 0)   & 3;
    const int r_b = (tid + 256) >> 2, q_b = (tid + 256) & 3;

    #define LOAD_STAGE(s, k0) do {                                              \
        const unsigned sA_ = sbase + (s) * STAGE_BYTES;                         \
        const unsigned sB_ = sA_ + TILE_BYTES;                                  \
        cpa16(sA_ + r_a * ROWB + q_a * 16, aug + (size_t)(m0 + r_a) * KA + (k0) + q_a * 8); \
        cpa16(sA_ + r_b * ROWB + q_b * 16, aug + (size_t)(m0 + r_b) * KA + (k0) + q_b * 8); \
        cpa16(sB_ + r_a * ROWB + q_a * 16, aug + (size_t)(n0 + r_a) * KA + (k0) + q_a * 8); \
        cpa16(sB_ + r_b * ROWB + q_b * 16, aug + (size_t)(n0 + r_b) * KA + (k0) + q_b * 8); \
    } while (0)

    #pragma unroll
    for (int s = 0; s < STAGES - 1; s++) {
        LOAD_STAGE(s, s * BK);
        asm volatile("cp.async.commit_group;" ::: "memory");
    }

    const int NK = KA / BK;  // 128
    const int rr = lane & 15;
    const unsigned coff = ((lane >> 4) << 3) * 2;   // +8 cols for hi half-warp

    for (int ks = 0; ks < NK; ks++) {
        asm volatile("cp.async.wait_group %0;" :: "n"(STAGES - 2) : "memory");
        __syncthreads();
        const int s = ks & (STAGES - 1);
        const unsigned stA = sbase + s * STAGE_BYTES + (wm * 64 + rr) * ROWB;
        const unsigned stB = sbase + s * STAGE_BYTES + TILE_BYTES + (wn * 32 + rr) * ROWB;
        #pragma unroll
        for (int h = 0; h < 2; h++) {
            const unsigned kb = h * 32 + coff;   // byte offset of k16 half
            unsigned a[4][4], bq[2][4];
            #pragma unroll
            for (int mb = 0; mb < 4; mb++) ldsm4(a[mb], stA + mb * (16 * ROWB) + kb);
            #pragma unroll
            for (int g = 0; g < 2; g++)    ldsm4(bq[g], stB + g * (16 * ROWB) + kb);
            #pragma unroll
            for (int mb = 0; mb < 4; mb++) {
                #pragma unroll
                for (int g = 0; g < 2; g++) {
                    mma16816(acc[mb][2*g],     a[mb], bq[g][0], bq[g][2]);
                    mma16816(acc[mb][2*g + 1], a[mb], bq[g][1], bq[g][3]);
                }
            }
        }
        const int kn = ks + STAGES - 1;
        if (kn < NK) LOAD_STAGE(kn & (STAGES - 1), kn * BK);
        asm volatile("cp.async.commit_group;" ::: "memory");
    }

    // ---- epilogue: distances + mining ----
    const float FINF = __int_as_float(0x7f800000);
    float sqj[8]; int tj[8];
    #pragma unroll
    for (int nb = 0; nb < 4; nb++)
        #pragma unroll
        for (int e = 0; e < 2; e++) {
            const int j = n0 + wn * 32 + nb * 8 + (lane & 3) * 2 + e;
            sqj[nb*2+e] = g_sq[j];
            tj[nb*2+e]  = g_tgt[j];
        }
    float cap[8], can[8];
    #pragma unroll
    for (int k = 0; k < 8; k++) { cap[k] = 0.f; can[k] = FINF; }

    #pragma unroll
    for (int mb = 0; mb < 4; mb++) {
        const int i0 = m0 + wm * 64 + mb * 16 + (lane >> 2);
        const float sqi0 = g_sq[i0], sqi1 = g_sq[i0 + 8];
        const int   ti0  = g_tgt[i0], ti1 = g_tgt[i0 + 8];
        float rap0 = 0.f, ran0 = FINF, rap1 = 0.f, ran1 = FINF;
        #pragma unroll
        for (int nb = 0; nb < 4; nb++) {
            #pragma unroll
            for (int e = 0; e < 2; e++) {
                const int   k  = nb * 2 + e;
                const float da = sqrtf(fmaxf(sqi0 + sqj[k] - 2.f * acc[mb][nb][e],     1e-12f));
                const float db = sqrtf(fmaxf(sqi1 + sqj[k] - 2.f * acc[mb][nb][2 + e], 1e-12f));
                if (ti0 == tj[k]) { rap0 = fmaxf(rap0, da); cap[k] = fmaxf(cap[k], da); }
                else              { ran0 = fminf(ran0, da); can[k] = fminf(can[k], da); }
                if (ti1 == tj[k]) { rap1 = fmaxf(rap1, db); cap[k] = fmaxf(cap[k], db); }
                else              { ran1 = fminf(ran1, db); can[k] = fminf(can[k], db); }
            }
        }
        #pragma unroll
        for (int o = 1; o <= 2; o <<= 1) {
            rap0 = fmaxf(rap0, __shfl_xor_sync(0xffffffffu, rap0, o));
            ran0 = fminf(ran0, __shfl_xor_sync(0xffffffffu, ran0, o));
            rap1 = fmaxf(rap1, __shfl_xor_sync(0xffffffffu, rap1, o));
            ran1 = fminf(ran1, __shfl_xor_sync(0xffffffffu, ran1, o));
        }
        if ((lane & 3) == 0) {
            const int li = wm * 64 + mb * 16 + (lane >> 2);
            atomicMax(&s_rap[li],     __float_as_uint(rap0));
            atomicMin(&s_ran[li],     __float_as_uint(ran0));
            atomicMax(&s_rap[li + 8], __float_as_uint(rap1));
            atomicMin(&s_ran[li + 8], __float_as_uint(ran1));
        }
    }
    if (mt != nt) {   // column-direction mining (d(i,j)=d(j,i)); diagonal redundant
        #pragma unroll
        for (int k = 0; k < 8; k++) {
            #pragma unroll
            for (int o = 4; o <= 16; o <<= 1) {
                cap[k] = fmaxf(cap[k], __shfl_xor_sync(0xffffffffu, cap[k], o));
                can[k] = fminf(can[k], __shfl_xor_sync(0xffffffffu, can[k], o));
            }
        }
        if ((lane >> 2) == 0) {
            #pragma unroll
            for (int nb = 0; nb < 4; nb++)
                #pragma unroll
                for (int e = 0; e < 2; e++) {
                    const int lj = wn * 32 + nb * 8 + (lane & 3) * 2 + e;
                    atomicMax(&s_cap[lj], __float_as_uint(cap[nb*2+e]));
                    atomicMin(&s_can[lj], __float_as_uint(can[nb*2+e]));
                }
        }
    }
    __syncthreads();
    if (tid < BM) {
        atomicMax(&g_ap[m0 + tid], s_rap[tid]);
        atomicMin(&g_an[m0 + tid], s_ran[tid]);
        if (mt != nt) {
            atomicMax(&g_ap[n0 + tid], s_cap[tid]);
            atomicMin(&g_an[n0 + tid], s_can[tid]);
        }
    }
    #undef LOAD_STAGE
}

// ---------------------------------------------------------------------------
__global__ void finalize_kernel(float* __restrict__ out) {
    float l = 0.f, p = 0.f;
    for (int i = threadIdx.x; i < NN; i += blockDim.x) {
        const float a = __uint_as_float(g_ap[i]);
        const float n = __uint_as_float(g_an[i]);
        l += fmaxf(a - n + 0.3f, 0.f);
        p += (n > a) ? 1.f : 0.f;
    }
    #pragma unroll
    for (int o = 16; o > 0; o >>= 1) {
        l += __shfl_xor_sync(0xffffffffu, l, o);
        p += __shfl_xor_sync(0xffffffffu, p, o);
    }
    __shared__ float wl[8], wp[8];
    const int lane = threadIdx.x & 31, w = threadIdx.x >> 5;
    if (lane == 0) { wl[w] = l; wp[w] = p; }
    __syncthreads();
    if (threadIdx.x == 0) {
        float L = 0.f, P = 0.f;
        #pragma unroll
        for (int i = 0; i < 8; i++) { L += wl[i]; P += wp[i]; }
        out[0] = L / (float)NN;
        out[1] = P / (float)NN;
    }
}

// ---------------------------------------------------------------------------
extern "C" void kernel_launch(void* const* d_in, const int* in_sizes, int n_in,
                              void* d_out, int out_size) {
    const float* A = (const float*)d_in[0];
    const int*   t = (const int*)d_in[1];
    float*     out = (float*)d_out;

    static int cfg_done = 0;
    if (!cfg_done) {
        cudaFuncSetAttribute(gram_kernel, cudaFuncAttributeMaxDynamicSharedMemorySize, SMEM_DYN);
        cfg_done = 1;
    }

    init_kernel<<<NN / 256, 256>>>();
    tgt_kernel<<<1, 256>>>(t);
    conv_kernel<<<NN, 256>>>(A);
    gram_kernel<<<NTILES, 256, SMEM_DYN>>>();
    finalize_kernel<<<1, 256>>>(out);
}

// round 5
// speedup vs baseline: 19.6296x; 2.1136x over previous
#include <cuda_runtime.h>
#include <cuda_bf16.h>
#include <math.h>

// Problem constants: inputs [4096, 2048] fp32, targets [4096]
#define NN 4096
#define DD 2048                 // K = 2048 bf16 (hi-only; lo half contributes < 2^-18)
#define BM 128
#define BN 128
#define BK 64
#define STAGES 3
#define ROWB 144                // 128B data + 16B pad: (9r+c) mod 8 permutation -> conflict-free
#define TILE_BYTES (BM * ROWB)          // 18432
#define STAGE_BYTES (2 * TILE_BYTES)    // A + B = 36864
#define SMEM_DYN (STAGES * STAGE_BYTES) // 110592
#define NTILES 528              // lower triangle incl. diagonal of 32x32 tiles

// Scratch (no cudaMalloc allowed)
__device__ __nv_bfloat16 g_hi[(size_t)NN * DD];   // 16MB, row-major
__device__ float        g_sq[NN];
__device__ int          g_tgt[NN];
__device__ unsigned int g_ap[NN];
__device__ unsigned int g_an[NN];

// ---------------------------------------------------------------------------
// helpers
// ---------------------------------------------------------------------------
__device__ __forceinline__ unsigned s2u(const void* p) {
    unsigned a;
    asm("{ .reg .u64 t; cvta.to.shared.u64 t, %1; cvt.u32.u64 %0, t; }" : "=r"(a) : "l"(p));
    return a;
}
__device__ __forceinline__ void cpa16(unsigned dst, const void* src) {
    unsigned long long g;
    asm("cvta.to.global.u64 %0, %1;" : "=l"(g) : "l"(src));
    asm volatile("cp.async.cg.shared.global [%0], [%1], 16;" :: "r"(dst), "l"(g));
}
__device__ __forceinline__ void ldsm4(unsigned* r, unsigned addr) {
    asm volatile("ldmatrix.sync.aligned.m8n8.x4.shared.b16 {%0,%1,%2,%3}, [%4];"
        : "=r"(r[0]), "=r"(r[1]), "=r"(r[2]), "=r"(r[3]) : "r"(addr));
}
__device__ __forceinline__ void mma16816(float* c, const unsigned* a, unsigned b0, unsigned b1) {
    asm volatile("mma.sync.aligned.m16n8k16.row.col.f32.bf16.bf16.f32 "
        "{%0,%1,%2,%3}, {%4,%5,%6,%7}, {%8,%9}, {%0,%1,%2,%3};"
        : "+f"(c[0]), "+f"(c[1]), "+f"(c[2]), "+f"(c[3])
        : "r"(a[0]), "r"(a[1]), "r"(a[2]), "r"(a[3]), "r"(b0), "r"(b1));
}

// ---------------------------------------------------------------------------
__global__ void init_kernel() {
    int i = blockIdx.x * blockDim.x + threadIdx.x;
    if (i < NN) { g_ap[i] = 0u; g_an[i] = 0x7f800000u; }
}

// Targets: int64 vs int32 detection (proven in the passing baselines)
__global__ void tgt_kernel(const int* __restrict__ t) {
    __shared__ int is64;
    if (threadIdx.x == 0) is64 = 1;
    __syncthreads();
    for (int i = threadIdx.x; i < NN / 2; i += blockDim.x)
        if (t[2 * i + 1] != 0) is64 = 0;
    __syncthreads();
    const int e = is64;
    for (int i = threadIdx.x; i < NN; i += blockDim.x)
        g_tgt[i] = e ? t[2 * i] : t[i];
}

// fp32 -> bf16 hi, row-major; fused exact fp32 row norms.
__global__ void conv_kernel(const float* __restrict__ A) {
    const int i = blockIdx.x;
    const int t = threadIdx.x;  // 0..255, cols [8t, 8t+8)
    const float4* ap = (const float4*)(A + (size_t)i * DD + t * 8);
    float4 v0 = ap[0], v1 = ap[1];
    float x[8] = {v0.x, v0.y, v0.z, v0.w, v1.x, v1.y, v1.z, v1.w};

    float s = 0.f;
    unsigned uh[4];
    #pragma unroll
    for (int q = 0; q < 4; q++) {
        float a0 = x[2*q], a1 = x[2*q+1];
        s += a0 * a0 + a1 * a1;
        __nv_bfloat16 h0 = __float2bfloat16_rn(a0);
        __nv_bfloat16 h1 = __float2bfloat16_rn(a1);
        uh[q] = (unsigned)__bfloat16_as_ushort(h0) | ((unsigned)__bfloat16_as_ushort(h1) << 16);
    }
    *(uint4*)(g_hi + (size_t)i * DD + t * 8) = make_uint4(uh[0], uh[1], uh[2], uh[3]);

    #pragma unroll
    for (int o = 16; o > 0; o >>= 1) s += __shfl_xor_sync(0xffffffffu, s, o);
    __shared__ float ws[8];
    const int lane = t & 31, w = t >> 5;
    if (lane == 0) ws[w] = s;
    __syncthreads();
    if (t == 0) {
        float tot = 0.f;
        #pragma unroll
        for (int k = 0; k < 8; k++) tot += ws[k];
        g_sq[i] = tot;
    }
}

// ---------------------------------------------------------------------------
// Fused Gram GEMM (mma.sync bf16, 128x128 tile, K=2048) + hard mining.
// 256 threads = 8 warps in 2x4; warp tile 64x32; triangular tiles with
// dual-direction (row + column) mining.
// ---------------------------------------------------------------------------
__global__ void __launch_bounds__(256) gram_kernel() {
    extern __shared__ unsigned char smem_dyn[];
    __shared__ unsigned s_rap[BM], s_ran[BM], s_cap[BN], s_can[BN];

    const int tid = threadIdx.x, lane = tid & 31, wid = tid >> 5;
    const int wm = wid >> 2, wn = wid & 3;

    // lower-triangle tile decode: id = mt(mt+1)/2 + nt
    int mt = 0, rem = blockIdx.x;
    while (rem >= mt + 1) { rem -= mt + 1; mt++; }
    const int nt = rem;
    const int m0 = mt * BM, n0 = nt * BN;

    const unsigned sbase = s2u(smem_dyn);
    const __nv_bfloat16* hi = g_hi;

    if (tid < BM) { s_rap[tid] = 0u; s_ran[tid] = 0x7f800000u; }
    if (tid < BN) { s_cap[tid] = 0u; s_can[tid] = 0x7f800000u; }

    float acc[4][4][4];
    #pragma unroll
    for (int a = 0; a < 4; a++)
        #pragma unroll
        for (int b = 0; b < 4; b++)
            #pragma unroll
            for (int c = 0; c < 4; c++) acc[a][b][c] = 0.f;

    // 1024 16B-quads per tile (128 rows x 8 quads); 4 slots each for A and B
    #define LOAD_STAGE(s, k0) do {                                              \
        const unsigned sA_ = sbase + (s) * STAGE_BYTES;                         \
        const unsigned sB_ = sA_ + TILE_BYTES;                                  \
        _Pragma("unroll")                                                       \
        for (int s4 = 0; s4 < 4; s4++) {                                        \
            const int idx = tid + s4 * 256;                                     \
            const int r = idx >> 3, q = idx & 7;                                \
            cpa16(sA_ + r * ROWB + q * 16, hi + (size_t)(m0 + r) * DD + (k0) + q * 8); \
            cpa16(sB_ + r * ROWB + q * 16, hi + (size_t)(n0 + r) * DD + (k0) + q * 8); \
        }                                                                       \
    } while (0)

    #pragma unroll
    for (int s = 0; s < STAGES - 1; s++) {
        LOAD_STAGE(s, s * BK);
        asm volatile("cp.async.commit_group;" ::: "memory");
    }

    const int NK = DD / BK;  // 32
    const int rr = lane & 15;
    const unsigned coff = ((lane >> 4) << 4);   // +16B for hi half-warp

    int sidx = 0;
    for (int ks = 0; ks < NK; ks++) {
        asm volatile("cp.async.wait_group %0;" :: "n"(STAGES - 2) : "memory");
        __syncthreads();
        const unsigned stA = sbase + sidx * STAGE_BYTES + (wm * 64 + rr) * ROWB;
        const unsigned stB = sbase + sidx * STAGE_BYTES + TILE_BYTES + (wn * 32 + rr) * ROWB;
        #pragma unroll
        for (int h = 0; h < 4; h++) {
            const unsigned kb = h * 32 + coff;   // byte offset of k16 chunk
            unsigned a[4][4], bq[2][4];
            #pragma unroll
            for (int mb = 0; mb < 4; mb++) ldsm4(a[mb], stA + mb * (16 * ROWB) + kb);
            #pragma unroll
            for (int g = 0; g < 2; g++)    ldsm4(bq[g], stB + g * (16 * ROWB) + kb);
            #pragma unroll
            for (int mb = 0; mb < 4; mb++) {
                #pragma unroll
                for (int g = 0; g < 2; g++) {
                    mma16816(acc[mb][2*g],     a[mb], bq[g][0], bq[g][2]);
                    mma16816(acc[mb][2*g + 1], a[mb], bq[g][1], bq[g][3]);
                }
            }
        }
        const int kn = ks + STAGES - 1;
        if (kn < NK) {
            int sl = kn;  // stage slot = kn mod STAGES
            while (sl >= STAGES) sl -= STAGES;
            LOAD_STAGE(sl, kn * BK);
        }
        asm volatile("cp.async.commit_group;" ::: "memory");
        if (++sidx == STAGES) sidx = 0;
    }

    // ---- epilogue: distances + mining ----
    const float FINF = __int_as_float(0x7f800000);
    float sqj[8]; int tj[8];
    #pragma unroll
    for (int nb = 0; nb < 4; nb++)
        #pragma unroll
        for (int e = 0; e < 2; e++) {
            const int j = n0 + wn * 32 + nb * 8 + (lane & 3) * 2 + e;
            sqj[nb*2+e] = g_sq[j];
            tj[nb*2+e]  = g_tgt[j];
        }
    float cap[8], can[8];
    #pragma unroll
    for (int k = 0; k < 8; k++) { cap[k] = 0.f; can[k] = FINF; }

    #pragma unroll
    for (int mb = 0; mb < 4; mb++) {
        const int i0 = m0 + wm * 64 + mb * 16 + (lane >> 2);
        const float sqi0 = g_sq[i0], sqi1 = g_sq[i0 + 8];
        const int   ti0  = g_tgt[i0], ti1 = g_tgt[i0 + 8];
        float rap0 = 0.f, ran0 = FINF, rap1 = 0.f, ran1 = FINF;
        #pragma unroll
        for (int nb = 0; nb < 4; nb++) {
            #pragma unroll
            for (int e = 0; e < 2; e++) {
                const int   k  = nb * 2 + e;
                const float da = sqrtf(fmaxf(sqi0 + sqj[k] - 2.f * acc[mb][nb][e],     1e-12f));
                const float db = sqrtf(fmaxf(sqi1 + sqj[k] - 2.f * acc[mb][nb][2 + e], 1e-12f));
                if (ti0 == tj[k]) { rap0 = fmaxf(rap0, da); cap[k] = fmaxf(cap[k], da); }
                else              { ran0 = fminf(ran0, da); can[k] = fminf(can[k], da); }
                if (ti1 == tj[k]) { rap1 = fmaxf(rap1, db); cap[k] = fmaxf(cap[k], db); }
                else              { ran1 = fminf(ran1, db); can[k] = fminf(can[k], db); }
            }
        }
        #pragma unroll
        for (int o = 1; o <= 2; o <<= 1) {
            rap0 = fmaxf(rap0, __shfl_xor_sync(0xffffffffu, rap0, o));
            ran0 = fminf(ran0, __shfl_xor_sync(0xffffffffu, ran0, o));
            rap1 = fmaxf(rap1, __shfl_xor_sync(0xffffffffu, rap1, o));
            ran1 = fminf(ran1, __shfl_xor_sync(0xffffffffu, ran1, o));
        }
        if ((lane & 3) == 0) {
            const int li = wm * 64 + mb * 16 + (lane >> 2);
            atomicMax(&s_rap[li],     __float_as_uint(rap0));
            atomicMin(&s_ran[li],     __float_as_uint(ran0));
            atomicMax(&s_rap[li + 8], __float_as_uint(rap1));
            atomicMin(&s_ran[li + 8], __float_as_uint(ran1));
        }
    }
    if (mt != nt) {   // column-direction mining (d(i,j)=d(j,i)); diagonal redundant
        #pragma unroll
        for (int k = 0; k < 8; k++) {
            #pragma unroll
            for (int o = 4; o <= 16; o <<= 1) {
                cap[k] = fmaxf(cap[k], __shfl_xor_sync(0xffffffffu, cap[k], o));
                can[k] = fminf(can[k], __shfl_xor_sync(0xffffffffu, can[k], o));
            }
        }
        if ((lane >> 2) == 0) {
            #pragma unroll
            for (int nb = 0; nb < 4; nb++)
                #pragma unroll
                for (int e = 0; e < 2; e++) {
                    const int lj = wn * 32 + nb * 8 + (lane & 3) * 2 + e;
                    atomicMax(&s_cap[lj], __float_as_uint(cap[nb*2+e]));
                    atomicMin(&s_can[lj], __float_as_uint(can[nb*2+e]));
                }
        }
    }
    __syncthreads();
    if (tid < BM) {
        atomicMax(&g_ap[m0 + tid], s_rap[tid]);
        atomicMin(&g_an[m0 + tid], s_ran[tid]);
        if (mt != nt) {
            atomicMax(&g_ap[n0 + tid], s_cap[tid]);
            atomicMin(&g_an[n0 + tid], s_can[tid]);
        }
    }
    #undef LOAD_STAGE
}

// ---------------------------------------------------------------------------
__global__ void finalize_kernel(float* __restrict__ out) {
    float l = 0.f, p = 0.f;
    for (int i = threadIdx.x; i < NN; i += blockDim.x) {
        const float a = __uint_as_float(g_ap[i]);
        const float n = __uint_as_float(g_an[i]);
        l += fmaxf(a - n + 0.3f, 0.f);
        p += (n > a) ? 1.f : 0.f;
    }
    #pragma unroll
    for (int o = 16; o > 0; o >>= 1) {
        l += __shfl_xor_sync(0xffffffffu, l, o);
        p += __shfl_xor_sync(0xffffffffu, p, o);
    }
    __shared__ float wl[8], wp[8];
    const int lane = threadIdx.x & 31, w = threadIdx.x >> 5;
    if (lane == 0) { wl[w] = l; wp[w] = p; }
    __syncthreads();
    if (threadIdx.x == 0) {
        float L = 0.f, P = 0.f;
        #pragma unroll
        for (int i = 0; i < 8; i++) { L += wl[i]; P += wp[i]; }
        out[0] = L / (float)NN;
        out[1] = P / (float)NN;
    }
}

// ---------------------------------------------------------------------------
extern "C" void kernel_launch(void* const* d_in, const int* in_sizes, int n_in,
                              void* d_out, int out_size) {
    const float* A = (const float*)d_in[0];
    const int*   t = (const int*)d_in[1];
    float*     out = (float*)d_out;

    static int cfg_done = 0;
    if (!cfg_done) {
        cudaFuncSetAttribute(gram_kernel, cudaFuncAttributeMaxDynamicSharedMemorySize, SMEM_DYN);
        cfg_done = 1;
    }

    init_kernel<<<NN / 256, 256>>>();
    tgt_kernel<<<1, 256>>>(t);
    conv_kernel<<<NN, 256>>>(A);
    gram_kernel<<<NTILES, 256, SMEM_DYN>>>();
    finalize_kernel<<<1, 256>>>(out);
}